// round 17
// baseline (speedup 1.0000x reference)
#include <cuda_runtime.h>
#include <cuda_fp16.h>
#include <math.h>
#include <stdint.h>

#define B_SZ   4
#define LEN    4096
#define HID    1024
#define STATE  16
#define INNER  2048
#define M_TOT  (B_SZ * LEN)
#define NC     16
#define LC     256
#define LOG2E  1.4426950408889634f

// ---------------- scratch ----------------
__device__ __align__(1024) float    g_Bm  [(size_t)M_TOT * STATE];
__device__ __align__(1024) float    g_Cm  [(size_t)M_TOT * STATE];
__device__ __align__(1024) uint32_t g_S2  [(size_t)B_SZ * NC * 8 * INNER];
__device__ __align__(1024) float    g_dts [(size_t)B_SZ * NC * INNER];
__device__ __align__(1024) float    g_H0  [(size_t)B_SZ * NC * STATE * INNER];
__device__ __align__(1024) __half   g_xph [(size_t)M_TOT * INNER];
__device__ __align__(1024) __half   g_zh  [(size_t)M_TOT * INNER];
__device__ __align__(1024) __half   g_dth [(size_t)M_TOT * INNER];
__device__ __align__(1024) __half   g_x0h [(size_t)M_TOT * HID];
__device__ __align__(1024) __half   g_wh  [(size_t)2 * INNER * HID];
__device__ __align__(1024) __half   g_dtwh[(size_t)INNER * INNER];
__device__ __align__(1024) __half   g_xch [(size_t)M_TOT * INNER];
__device__ __align__(1024) __half   g_y0h [(size_t)M_TOT * INNER];
__device__ __align__(1024) __half   g_owh [(size_t)HID * INNER];
__device__ __align__(1024) __half   g_wbch[32 * INNER];

// ---------------- PTX helpers ----------------
__device__ __forceinline__ uint32_t smem_u32(const void* p) {
    uint32_t a;
    asm("{ .reg .u64 t; cvta.to.shared.u64 t, %1; cvt.u32.u64 %0, t; }" : "=r"(a) : "l"(p));
    return a;
}
__device__ __forceinline__ void cp_async16(uint32_t dst, const void* src) {
    asm volatile("cp.async.cg.shared.global [%0], [%1], 16;" :: "r"(dst), "l"(src) : "memory");
}
#define CP_COMMIT() asm volatile("cp.async.commit_group;" ::: "memory")
#define CP_WAIT1()  asm volatile("cp.async.wait_group 1;" ::: "memory")

__device__ __forceinline__ void ldm_x4(uint32_t* r, uint32_t addr) {
    asm volatile("ldmatrix.sync.aligned.m8n8.x4.shared.b16 {%0,%1,%2,%3}, [%4];"
        : "=r"(r[0]), "=r"(r[1]), "=r"(r[2]), "=r"(r[3]) : "r"(addr));
}
__device__ __forceinline__ void mma16816h(float* d, const uint32_t* a, const uint32_t* b) {
    asm volatile("mma.sync.aligned.m16n8k16.row.col.f32.f16.f16.f32 "
        "{%0,%1,%2,%3}, {%4,%5,%6,%7}, {%8,%9}, {%0,%1,%2,%3};"
        : "+f"(d[0]), "+f"(d[1]), "+f"(d[2]), "+f"(d[3])
        : "r"(a[0]), "r"(a[1]), "r"(a[2]), "r"(a[3]), "r"(b[0]), "r"(b[1]));
}
__device__ __forceinline__ __half2 hexp2_x2(__half2 x) {
    __half2 r;
    asm("ex2.approx.f16x2 %0, %1;" : "=r"(*(uint32_t*)&r) : "r"(*(uint32_t*)&x));
    return r;
}
__device__ __forceinline__ float softplusf(float v) { return v > 20.f ? v : log1pf(__expf(v)); }
__device__ __forceinline__ float siluf(float v)     { return v / (1.f + __expf(-v)); }

// ---------------- fp16 mma.sync GEMM, 2 CTAs/SM tiling ----------------
#define GBM 128
#define GBN 128
#define GAST (GBM * 128)
#define GSTG (GAST + GBN * 128)
#define GSMEM (3 * GSTG)

template <int EPI>   // 0 = fp32 bias, 1 = fp16 softplus, 2 = fp16 bias
__global__ void __launch_bounds__(256, 2) gemm_mma(
    const __half* __restrict__ Ap, const __half* __restrict__ Bp,
    const float* __restrict__ bias, void* __restrict__ Cv, int Cstride, int K)
{
    extern __shared__ char smraw[];
    const uint32_t sbase = smem_u32(smraw);
    const int tid  = threadIdx.x;
    const int wid  = tid >> 5;
    const int lane = tid & 31;
    const int bm0  = blockIdx.y * GBM;
    const int bn0  = blockIdx.x * GBN;

    const int KTT = K >> 6;
    const size_t lda = (size_t)K * 2;

    auto load_stage = [&](int kt, int s) {
        const uint32_t sa = sbase + s * GSTG;
        const uint32_t sb = sa + GAST;
#pragma unroll
        for (int i = 0; i < 4; ++i) {
            int idx = tid + i * 256, r = idx >> 3, c = idx & 7;
            cp_async16(sa + r * 128 + ((c ^ (r & 7)) << 4),
                       (const char*)Ap + (size_t)(bm0 + r) * lda + (size_t)kt * 128 + c * 16);
        }
#pragma unroll
        for (int i = 0; i < 4; ++i) {
            int idx = tid + i * 256, r = idx >> 3, c = idx & 7;
            cp_async16(sb + r * 128 + ((c ^ (r & 7)) << 4),
                       (const char*)Bp + (size_t)(bn0 + r) * lda + (size_t)kt * 128 + c * 16);
        }
    };

    float acc[4][4][4];
#pragma unroll
    for (int mt = 0; mt < 4; ++mt)
#pragma unroll
        for (int nt = 0; nt < 4; ++nt)
#pragma unroll
            for (int q = 0; q < 4; ++q) acc[mt][nt][q] = 0.f;

    load_stage(0, 0); CP_COMMIT();
    load_stage(1, 1); CP_COMMIT();

    const int wm0 = (wid >> 2) * 64;
    const int wn0 = (wid & 3) * 32;
    const int aRow = wm0 + ((lane >> 3) & 1) * 8 + (lane & 7);
    const int bRow = wn0 + ((lane >> 4) & 1) * 8 + (lane & 7);
    const int swzX = (lane & 7) << 4;
    const int aKs  = (lane >> 4) << 4;
    const int bKs  = ((lane >> 3) & 1) << 4;

    for (int kt = 0; kt < KTT; ++kt) {
        const int s = kt % 3;
        CP_WAIT1();
        __syncthreads();
        if (kt + 2 < KTT) { load_stage(kt + 2, (kt + 2) % 3); CP_COMMIT(); }

        const uint32_t Ab = sbase + s * GSTG;
        const uint32_t Bb = Ab + GAST;
#pragma unroll
        for (int ks = 0; ks < 4; ++ks) {
            const int swA = (ks * 32 + aKs) ^ swzX;
            const int swB = (ks * 32 + bKs) ^ swzX;
            uint32_t a[4][4], b[2][4];
#pragma unroll
            for (int mt = 0; mt < 4; ++mt) ldm_x4(a[mt], Ab + (aRow + mt * 16) * 128 + swA);
#pragma unroll
            for (int np = 0; np < 2; ++np) ldm_x4(b[np], Bb + (bRow + np * 16) * 128 + swB);
#pragma unroll
            for (int mt = 0; mt < 4; ++mt)
#pragma unroll
                for (int nt = 0; nt < 4; ++nt)
                    mma16816h(acc[mt][nt], a[mt], &b[nt >> 1][(nt & 1) * 2]);
        }
    }

#pragma unroll
    for (int nt = 0; nt < 4; ++nt) {
        const int col = bn0 + wn0 + nt * 8 + (lane & 3) * 2;
        const float b0v = bias[col], b1v = bias[col + 1];
#pragma unroll
        for (int mt = 0; mt < 4; ++mt) {
            const int row = bm0 + wm0 + mt * 16 + (lane >> 2);
            float v0 = acc[mt][nt][0] + b0v, v1 = acc[mt][nt][1] + b1v;
            float v2 = acc[mt][nt][2] + b0v, v3 = acc[mt][nt][3] + b1v;
            if (EPI == 1) {
                v0 = softplusf(v0); v1 = softplusf(v1);
                v2 = softplusf(v2); v3 = softplusf(v3);
            }
            if (EPI == 0) {
                float* C = (float*)Cv;
                *reinterpret_cast<float2*>(&C[(size_t)row * Cstride + col])       = make_float2(v0, v1);
                *reinterpret_cast<float2*>(&C[(size_t)(row + 8) * Cstride + col]) = make_float2(v2, v3);
            } else {
                __half* C = (__half*)Cv;
                *reinterpret_cast<__half2*>(&C[(size_t)row * Cstride + col])       = __floats2half2_rn(v0, v1);
                *reinterpret_cast<__half2*>(&C[(size_t)(row + 8) * Cstride + col]) = __floats2half2_rn(v2, v3);
            }
        }
    }
}

// ---------------- B/C projection: BM=64, 128 threads, 2 stages x 12KB = 24KB ----------------
#define BCAST (64 * 128)
#define BCSTG (BCAST + 32 * 128)
#define BCSMEM (2 * BCSTG)
__global__ void __launch_bounds__(128, 1) bc_mma(
    const __half* __restrict__ A, const __half* __restrict__ W,
    const float* __restrict__ Bb, const float* __restrict__ Cb)
{
    extern __shared__ char smraw[];
    const uint32_t sbase = smem_u32(smraw);
    const int tid  = threadIdx.x;
    const int wid  = tid >> 5;
    const int lane = tid & 31;
    const int bm0  = blockIdx.x * 64;
    const size_t lda = (size_t)INNER * 2;

    auto load_stage = [&](int kt, int s) {
        const uint32_t sa = sbase + s * BCSTG;
        const uint32_t sb = sa + BCAST;
#pragma unroll
        for (int i = 0; i < 4; ++i) {
            int idx = tid + i * 128, r = idx >> 3, c = idx & 7;
            cp_async16(sa + r * 128 + ((c ^ (r & 7)) << 4),
                       (const char*)A + (size_t)(bm0 + r) * lda + (size_t)kt * 128 + c * 16);
        }
#pragma unroll
        for (int i = 0; i < 2; ++i) {
            int idx = tid + i * 128, r = idx >> 3, c = idx & 7;
            cp_async16(sb + r * 128 + ((c ^ (r & 7)) << 4),
                       (const char*)W + (size_t)r * lda + (size_t)kt * 128 + c * 16);
        }
    };

    float acc[4][4];
#pragma unroll
    for (int nt = 0; nt < 4; ++nt)
#pragma unroll
        for (int q = 0; q < 4; ++q) acc[nt][q] = 0.f;

    load_stage(0, 0); CP_COMMIT();
    load_stage(1, 1); CP_COMMIT();

    const int aRow = wid * 16 + ((lane >> 3) & 1) * 8 + (lane & 7);
    const int bRow = ((lane >> 4) & 1) * 8 + (lane & 7);
    const int swzX = (lane & 7) << 4;
    const int aKs  = (lane >> 4) << 4;
    const int bKs  = ((lane >> 3) & 1) << 4;

    const int KT = INNER / 64;
    for (int kt = 0; kt < KT; ++kt) {
        const int s = kt & 1;
        CP_WAIT1();
        __syncthreads();

        const uint32_t Ab = sbase + s * BCSTG;
        const uint32_t Bb_ = Ab + BCAST;
#pragma unroll
        for (int ks = 0; ks < 4; ++ks) {
            const int swA = (ks * 32 + aKs) ^ swzX;
            const int swB = (ks * 32 + bKs) ^ swzX;
            uint32_t a[4], b[2][4];
            ldm_x4(a, Ab + aRow * 128 + swA);
#pragma unroll
            for (int np = 0; np < 2; ++np) ldm_x4(b[np], Bb_ + (bRow + np * 16) * 128 + swB);
#pragma unroll
            for (int nt = 0; nt < 4; ++nt)
                mma16816h(acc[nt], a, &b[nt >> 1][(nt & 1) * 2]);
        }
        __syncthreads();
        if (kt + 2 < KT) { load_stage(kt + 2, s); CP_COMMIT(); }
    }

#pragma unroll
    for (int nt = 0; nt < 4; ++nt) {
        const int col = nt * 8 + (lane & 3) * 2;
        const int row = bm0 + wid * 16 + (lane >> 2);
        if (col < 16) {
            const float c0 = Bb[col], c1 = Bb[col + 1];
            *reinterpret_cast<float2*>(&g_Bm[(size_t)row * 16 + col]) =
                make_float2(acc[nt][0] + c0, acc[nt][1] + c1);
            *reinterpret_cast<float2*>(&g_Bm[(size_t)(row + 8) * 16 + col]) =
                make_float2(acc[nt][2] + c0, acc[nt][3] + c1);
        } else {
            const int cc = col - 16;
            const float c0 = Cb[cc], c1 = Cb[cc + 1];
            *reinterpret_cast<float2*>(&g_Cm[(size_t)row * 16 + cc]) =
                make_float2(acc[nt][0] + c0, acc[nt][1] + c1);
            *reinterpret_cast<float2*>(&g_Cm[(size_t)(row + 8) * 16 + cc]) =
                make_float2(acc[nt][2] + c0, acc[nt][3] + c1);
        }
    }
}

// ---------------- conversions: x + all weights in ONE launch ----------------
__global__ void __launch_bounds__(256) cvtall_kernel(
    const float* __restrict__ xs, const float* __restrict__ w1, const float* __restrict__ w2,
    const float* __restrict__ w3, const float* __restrict__ w4, const float* __restrict__ w5,
    __half* __restrict__ ox, __half* __restrict__ o1, __half* __restrict__ o2,
    __half* __restrict__ o3, __half* __restrict__ o4)
{
    const size_t n0 = (size_t)M_TOT * HID / 4;
    const size_t n1 = (size_t)2 * INNER * HID / 4;
    const size_t n2 = (size_t)INNER * INNER / 4;
    const size_t n3 = (size_t)HID * INNER / 4;
    const size_t n4 = (size_t)16 * INNER / 4;
    const size_t nt = n0 + n1 + n2 + n3 + 2 * n4;
    for (size_t i = (size_t)blockIdx.x * 256 + threadIdx.x; i < nt;
         i += (size_t)gridDim.x * 256) {
        const float* src; __half* dst; size_t j;
        if (i < n0)                      { src = xs; dst = ox; j = i; }
        else if (i < n0 + n1)            { src = w1; dst = o1; j = i - n0; }
        else if (i < n0 + n1 + n2)       { src = w2; dst = o2; j = i - n0 - n1; }
        else if (i < n0 + n1 + n2 + n3)  { src = w3; dst = o3; j = i - n0 - n1 - n2; }
        else if (i < n0 + n1 + n2 + n3 + n4) { src = w4; dst = o4; j = i - n0 - n1 - n2 - n3; }
        else { src = w5; dst = o4 + (size_t)16 * INNER; j = i - n0 - n1 - n2 - n3 - n4; }
        float4 v = reinterpret_cast<const float4*>(src)[j];
        ((ushort4*)dst)[j] = make_ushort4(
            __half_as_ushort(__float2half_rn(v.x)), __half_as_ushort(__float2half_rn(v.y)),
            __half_as_ushort(__float2half_rn(v.z)), __half_as_ushort(__float2half_rn(v.w)));
    }
}

// ---------------- causal depthwise conv (K=4) + SiLU, 8 ch/thread, 16 rows/CTA ----------------
// block 256 threads (cover INNER=2048 channels), grid (LEN/16, B).
__global__ void __launch_bounds__(256) conv_silu_kernel(
    const float* __restrict__ conv_w, const float* __restrict__ conv_b)
{
    const int g8 = threadIdx.x;
    const int l0 = blockIdx.x * 16;
    const int b  = blockIdx.y;
    const int d  = g8 * 8;

    float w[4][8], cb[8];
#pragma unroll
    for (int j = 0; j < 8; ++j) {
        w[0][j] = conv_w[(d + j) * 4 + 0];
        w[1][j] = conv_w[(d + j) * 4 + 1];
        w[2][j] = conv_w[(d + j) * 4 + 2];
        w[3][j] = conv_w[(d + j) * 4 + 3];
        cb[j]   = conv_b[d + j];
    }

    const uint4* xp = (const uint4*)g_xph + (size_t)(b * LEN) * (INNER / 8) + g8;
    uint4*       xo = (uint4*)g_xch       + (size_t)(b * LEN) * (INNER / 8) + g8;

    float m[3][8];
#pragma unroll
    for (int t = 0; t < 3; ++t) {
        if (l0 == 0) {
#pragma unroll
            for (int j = 0; j < 8; ++j) m[t][j] = 0.f;
        } else {
            uint4 v = xp[(size_t)(l0 - 3 + t) * (INNER / 8)];
            const __half2* h = (const __half2*)&v;
#pragma unroll
            for (int p = 0; p < 4; ++p) {
                float2 f = __half22float2(h[p]);
                m[t][2 * p] = f.x; m[t][2 * p + 1] = f.y;
            }
        }
    }

#pragma unroll 4
    for (int i = 0; i < 16; ++i) {
        uint4 v = xp[(size_t)(l0 + i) * (INNER / 8)];
        const __half2* h = (const __half2*)&v;
        float cur[8];
#pragma unroll
        for (int p = 0; p < 4; ++p) {
            float2 f = __half22float2(h[p]);
            cur[2 * p] = f.x; cur[2 * p + 1] = f.y;
        }
        uint4 o;
        __half2* oh = (__half2*)&o;
#pragma unroll
        for (int p = 0; p < 4; ++p) {
            int j0 = 2 * p, j1 = 2 * p + 1;
            float v0 = w[0][j0] * m[0][j0] + w[1][j0] * m[1][j0] + w[2][j0] * m[2][j0]
                     + w[3][j0] * cur[j0] + cb[j0];
            float v1 = w[0][j1] * m[0][j1] + w[1][j1] * m[1][j1] + w[2][j1] * m[2][j1]
                     + w[3][j1] * cur[j1] + cb[j1];
            oh[p] = __floats2half2_rn(siluf(v0), siluf(v1));
        }
        xo[(size_t)(l0 + i) * (INNER / 8)] = o;
#pragma unroll
        for (int j = 0; j < 8; ++j) { m[0][j] = m[1][j]; m[1][j] = m[2][j]; m[2][j] = cur[j]; }
    }
}

// ---------------- chunked selective scan ----------------
__global__ void __launch_bounds__(128) scanA_kernel(const float* __restrict__ A_log)
{
    __shared__ uint32_t sBh[LC * 8];
    const int d = blockIdx.x * 128 + threadIdx.x;
    const int c = blockIdx.y;
    const int b = blockIdx.z;
    const int base_l = c * LC;
    for (int i = threadIdx.x; i < LC * 8; i += 128) {
        const float2 v = *reinterpret_cast<const float2*>(
            &g_Bm[(size_t)(b * LEN + base_l) * STATE + 2 * i]);
        __half2 hh = __floats2half2_rn(v.x, v.y);
        sBh[i] = *reinterpret_cast<uint32_t*>(&hh);
    }
    __syncthreads();
    __half2 Ar2[8];
#pragma unroll
    for (int i = 0; i < 8; i++)
        Ar2[i] = __floats2half2_rn(-expf(A_log[d * STATE + 2 * i]) * LOG2E,
                                   -expf(A_log[d * STATE + 2 * i + 1]) * LOG2E);
    __half2 h2[8];
#pragma unroll
    for (int i = 0; i < 8; i++) h2[i] = __floats2half2_rn(0.f, 0.f);
    float dtsum = 0.f;
    const __half* dtp = g_dth + (size_t)(b * LEN + base_l) * INNER + d;
    const __half* xcp = g_xch + (size_t)(b * LEN + base_l) * INNER + d;
    for (int l = 0; l < LC; ++l) {
        __half dtv = dtp[(size_t)l * INNER];
        __half xv  = xcp[(size_t)l * INNER];
        dtsum += __half2float(dtv);
        __half2 dt2  = __half2half2(dtv);
        __half2 dtx2 = __half2half2(__hmul(dtv, xv));
#pragma unroll
        for (int i = 0; i < 8; i++) {
            __half2 dA  = hexp2_x2(__hmul2(dt2, Ar2[i]));
            __half2 inc = __hmul2(*reinterpret_cast<const __half2*>(&sBh[l * 8 + i]), dtx2);
            h2[i] = __hfma2(dA, h2[i], inc);
        }
    }
    size_t sb2 = (size_t)(b * NC + c) * 8 * INNER + d;
#pragma unroll
    for (int i = 0; i < 8; i++)
        g_S2[sb2 + (size_t)i * INNER] = *reinterpret_cast<uint32_t*>(&h2[i]);
    g_dts[(size_t)(b * NC + c) * INNER + d] = dtsum;
}

__global__ void __launch_bounds__(256) scanB_kernel(const float* __restrict__ A_log)
{
    int g = blockIdx.x * 256 + threadIdx.x;
    int i = g & 7;
    int t = g >> 3;
    int b = t / INNER;
    int d = t - b * INNER;
    float Ar0 = -expf(A_log[d * STATE + 2 * i]);
    float Ar1 = -expf(A_log[d * STATE + 2 * i + 1]);
    float h0 = 0.f, h1 = 0.f;
    for (int c = 0; c < NC; ++c) {
        size_t hb = (size_t)(b * NC + c) * STATE * INNER + d;
        g_H0[hb + (size_t)(2 * i) * INNER]     = h0;
        g_H0[hb + (size_t)(2 * i + 1) * INNER] = h1;
        float ds = g_dts[(size_t)(b * NC + c) * INNER + d];
        uint32_t sv = g_S2[(size_t)(b * NC + c) * 8 * INNER + (size_t)i * INNER + d];
        float2 svf = __half22float2(*reinterpret_cast<__half2*>(&sv));
        h0 = __expf(Ar0 * ds) * h0 + svf.x;
        h1 = __expf(Ar1 * ds) * h1 + svf.y;
    }
}

__global__ void __launch_bounds__(128) scanC_kernel(
    const float* __restrict__ A_log, const float* __restrict__ Dv)
{
    __shared__ uint32_t sBh[LC * 8];
    __shared__ uint32_t sCh[LC * 8];
    const int d = blockIdx.x * 128 + threadIdx.x;
    const int c = blockIdx.y;
    const int b = blockIdx.z;
    const int base_l = c * LC;
    for (int i = threadIdx.x; i < LC * 8; i += 128) {
        const float2 vb = *reinterpret_cast<const float2*>(
            &g_Bm[(size_t)(b * LEN + base_l) * STATE + 2 * i]);
        const float2 vc = *reinterpret_cast<const float2*>(
            &g_Cm[(size_t)(b * LEN + base_l) * STATE + 2 * i]);
        __half2 hb = __floats2half2_rn(vb.x, vb.y);
        __half2 hc = __floats2half2_rn(vc.x, vc.y);
        sBh[i] = *reinterpret_cast<uint32_t*>(&hb);
        sCh[i] = *reinterpret_cast<uint32_t*>(&hc);
    }
    __syncthreads();
    __half2 Ar2[8];
#pragma unroll
    for (int i = 0; i < 8; i++)
        Ar2[i] = __floats2half2_rn(-expf(A_log[d * STATE + 2 * i]) * LOG2E,
                                   -expf(A_log[d * STATE + 2 * i + 1]) * LOG2E);
    const float Dd = Dv[d];
    __half2 h2[8];
    size_t ob = (size_t)(b * NC + c) * STATE * INNER + d;
#pragma unroll
    for (int i = 0; i < 8; i++)
        h2[i] = __floats2half2_rn(g_H0[ob + (size_t)(2 * i) * INNER],
                                  g_H0[ob + (size_t)(2 * i + 1) * INNER]);
    const __half* dtp = g_dth + (size_t)(b * LEN + base_l) * INNER + d;
    const __half* xcp = g_xch + (size_t)(b * LEN + base_l) * INNER + d;
    const __half* zp  = g_zh  + (size_t)(b * LEN + base_l) * INNER + d;
    __half* y0p = g_y0h + (size_t)(b * LEN + base_l) * INNER + d;
    for (int l = 0; l < LC; ++l) {
        __half dtv = dtp[(size_t)l * INNER];
        __half xv  = xcp[(size_t)l * INNER];
        float zv   = __half2float(zp[(size_t)l * INNER]);
        __half2 dt2  = __half2half2(dtv);
        __half2 dtx2 = __half2half2(__hmul(dtv, xv));
        __half2 acc2 = __floats2half2_rn(0.f, 0.f);
#pragma unroll
        for (int i = 0; i < 8; i++) {
            __half2 dA  = hexp2_x2(__hmul2(dt2, Ar2[i]));
            __half2 inc = __hmul2(*reinterpret_cast<const __half2*>(&sBh[l * 8 + i]), dtx2);
            h2[i] = __hfma2(dA, h2[i], inc);
            acc2  = __hfma2(*reinterpret_cast<const __half2*>(&sCh[l * 8 + i]), h2[i], acc2);
        }
        float acc = __low2float(acc2) + __high2float(acc2) + Dd * __half2float(xv);
        y0p[(size_t)l * INNER] = __float2half_rn(acc * siluf(zv));
    }
}

// ---------------- launch ----------------
extern "C" void kernel_launch(void* const* d_in, const int* in_sizes, int n_in,
                              void* d_out, int out_size)
{
    const float* x      = (const float*)d_in[0];
    const float* in_w   = (const float*)d_in[1];
    const float* in_b   = (const float*)d_in[2];
    const float* conv_w = (const float*)d_in[3];
    const float* conv_b = (const float*)d_in[4];
    const float* dt_w   = (const float*)d_in[5];
    const float* dt_b   = (const float*)d_in[6];
    const float* A_log  = (const float*)d_in[7];
    const float* B_w    = (const float*)d_in[8];
    const float* B_b    = (const float*)d_in[9];
    const float* C_w    = (const float*)d_in[10];
    const float* C_b    = (const float*)d_in[11];
    const float* Dv     = (const float*)d_in[12];
    const float* out_w  = (const float*)d_in[13];
    const float* out_b  = (const float*)d_in[14];
    float* out = (float*)d_out;

    __half *x0h, *wh, *dtwh, *xch, *y0h, *owh, *wbch, *zh, *dth, *xph;
    cudaGetSymbolAddress((void**)&xph, g_xph);
    cudaGetSymbolAddress((void**)&x0h, g_x0h);
    cudaGetSymbolAddress((void**)&wh, g_wh);
    cudaGetSymbolAddress((void**)&dtwh, g_dtwh);
    cudaGetSymbolAddress((void**)&xch, g_xch);
    cudaGetSymbolAddress((void**)&y0h, g_y0h);
    cudaGetSymbolAddress((void**)&owh, g_owh);
    cudaGetSymbolAddress((void**)&wbch, g_wbch);
    cudaGetSymbolAddress((void**)&zh, g_zh);
    cudaGetSymbolAddress((void**)&dth, g_dth);

    cudaFuncSetAttribute(gemm_mma<1>, cudaFuncAttributeMaxDynamicSharedMemorySize, GSMEM);
    cudaFuncSetAttribute(gemm_mma<0>, cudaFuncAttributeMaxDynamicSharedMemorySize, GSMEM);
    cudaFuncSetAttribute(gemm_mma<2>, cudaFuncAttributeMaxDynamicSharedMemorySize, GSMEM);
    cudaFuncSetAttribute(bc_mma, cudaFuncAttributeMaxDynamicSharedMemorySize, BCSMEM);

    static cudaStream_t s1 = nullptr;
    static cudaEvent_t evA = nullptr, evZ = nullptr, evC = nullptr, evB = nullptr;
    if (s1 == nullptr) {
        cudaStreamCreateWithFlags(&s1, cudaStreamNonBlocking);
        cudaEventCreateWithFlags(&evA, cudaEventDisableTiming);
        cudaEventCreateWithFlags(&evZ, cudaEventDisableTiming);
        cudaEventCreateWithFlags(&evC, cudaEventDisableTiming);
        cudaEventCreateWithFlags(&evB, cudaEventDisableTiming);
    }

    // 0) all fp16 conversions in one launch
    cvtall_kernel<<<2048, 256>>>(x, in_w, dt_w, out_w, B_w, C_w,
                                 x0h, wh, dtwh, owh, wbch);
    cudaEventRecord(evA, 0);

    // fork: z half of in-proj on s1
    cudaStreamWaitEvent(s1, evA, 0);
    gemm_mma<2><<<dim3(INNER / GBN, M_TOT / GBM), 256, GSMEM, s1>>>(
        x0h, wh + (size_t)INNER * HID, in_b + INNER, zh, INNER, HID);
    cudaEventRecord(evZ, s1);

    // 1) in-proj x_part half -> fp16                       (16384 x 2048 x 1024)
    gemm_mma<2><<<dim3(INNER / GBN, M_TOT / GBM), 256, GSMEM>>>(
        x0h, wh, in_b, xph, INNER, HID);

    // 2) conv + silu (uint4, 16 rows/CTA for latency hiding)
    conv_silu_kernel<<<dim3(LEN / 16, B_SZ), 256>>>(conv_w, conv_b);
    cudaEventRecord(evC, 0);

    // 3) B/C projections on s1, co-residing with the dt GEMM (24KB CTAs)
    cudaStreamWaitEvent(s1, evC, 0);
    bc_mma<<<M_TOT / 64, 128, BCSMEM, s1>>>(xch, wbch, B_b, C_b);
    cudaEventRecord(evB, s1);

    // 4) dt = softplus(xconv @ dt_w^T + dt_b) -> fp16      (16384 x 2048 x 2048)
    gemm_mma<1><<<dim3(INNER / GBN, M_TOT / GBM), 256, GSMEM>>>(
        xch, dtwh, dt_b, dth, INNER, INNER);

    // 5) chunked selective scan + gating
    cudaStreamWaitEvent(0, evB, 0);
    scanA_kernel<<<dim3(INNER / 128, NC, B_SZ), 128>>>(A_log);
    scanB_kernel<<<(B_SZ * INNER * 8) / 256, 256>>>(A_log);
    cudaStreamWaitEvent(0, evZ, 0);
    scanC_kernel<<<dim3(INNER / 128, NC, B_SZ), 128>>>(A_log, Dv);

    // 6) out-proj: out = y @ out_w^T + out_b               (16384 x 1024 x 2048)
    gemm_mma<0><<<dim3(HID / GBN, M_TOT / GBM), 256, GSMEM>>>(
        y0h, owh, out_b, out, HID, INNER);
}